// round 4
// baseline (speedup 1.0000x reference)
#include <cuda_runtime.h>
#include <stdint.h>

#define NN    50000
#define NE    800000
#define ET    (NE + NN)      // 850000
#define OD    40
#define NEG_SLOPE 0.2f
#define NB    49             // ceil(NN/1024) scan blocks

typedef unsigned long long ull;

// ---------------- scratch ----------------
__device__ float4 g_h1[NN * 32];      // [NN][128]
__device__ float4 g_acc1[NN * 32];    // [NN][128]
__device__ float4 g_as1[NN];
__device__ float4 g_ad1[NN];
__device__ float4 g_h2[NN * 10];      // [NN][40]
__device__ float  g_as2[NN];
__device__ float  g_ad2[NN];
__device__ float2 g_wsd[128];         // {W2@a2s, W2@a2d}[k]
// CSR
__device__ int    g_deg[NN];
__device__ int    g_cursor[NN];
__device__ int    g_incl[NN];
__device__ int    g_bsum[64];
__device__ int    g_bscan[64];
__device__ int    g_ptr[NN];
__device__ int    g_esrc[ET];

// ---------------- helpers ----------------
__device__ __forceinline__ float lrelu(float v) { return v > 0.f ? v : NEG_SLOPE * v; }

__device__ __forceinline__ ull pack2(float lo, float hi) {
    ull r; asm("mov.b64 %0, {%1, %2};" : "=l"(r) : "f"(lo), "f"(hi)); return r;
}
__device__ __forceinline__ void unpack2(ull v, float& lo, float& hi) {
    asm("mov.b64 {%0, %1}, %2;" : "=f"(lo), "=f"(hi) : "l"(v));
}
__device__ __forceinline__ void fma2(ull& acc, ull a, ull b) {
    asm("fma.rn.f32x2 %0, %1, %2, %0;" : "+l"(acc) : "l"(a), "l"(b));
}
__device__ __forceinline__ void edge_sd(const int* __restrict__ ei, int e, int& s, int& d) {
    if (e < NE) { s = ei[e]; d = ei[NE + e]; }
    else        { s = d = e - NE; }
}

// ---------------- init: zero CSR counters + fold a2s/a2d into W2 columns ----------------
__global__ void k_zero_prep(const float* __restrict__ W2,
                            const float* __restrict__ a2s, const float* __restrict__ a2d) {
    int i = blockIdx.x * blockDim.x + threadIdx.x;
    if (i < NN) { g_deg[i] = 0; g_cursor[i] = 0; }
    if (blockIdx.x == 0 && threadIdx.x < 128) {
        int k = threadIdx.x;
        float ws = 0.f, wd = 0.f;
#pragma unroll 8
        for (int c = 0; c < OD; c++) {
            float w = W2[k * OD + c];
            ws += w * a2s[c];
            wd += w * a2d[c];
        }
        g_wsd[k] = make_float2(ws, wd);
    }
}

// ---------------- GEMM1 (f32x2) + fused degree histogram ----------------
// 64 rows/block, thread tile = 4 rows x 8 cols (4 col-pairs). 782 blocks x 256.
__global__ void __launch_bounds__(256) k_gemm1(
    const float* __restrict__ x, const float* __restrict__ W1,
    const float* __restrict__ a_src, const float* __restrict__ a_dst,
    const int* __restrict__ ei)
{
    __shared__ float xs[64][128];   // 32KB
    int t = threadIdx.x;
    int row0 = blockIdx.x * 64;

    // fused histogram slice (independent of gemm data; overlaps other blocks' compute)
    {
        const int S = (ET + gridDim.x - 1) / gridDim.x;
        int e0 = blockIdx.x * S;
        int e1 = min(ET, e0 + S);
        for (int e = e0 + t; e < e1; e += 256) {
            int d = (e < NE) ? ei[NE + e] : (e - NE);
            atomicAdd(&g_deg[d], 1);
        }
    }

    // stage 64 rows of x
    for (int i = t; i < 64 * 32; i += 256) {
        int r = i >> 5, kc = i & 31;
        int gr = min(row0 + r, NN - 1);
        float4 v = ((const float4*)x)[gr * 32 + kc];
        *(float4*)&xs[r][kc * 4] = v;
    }
    __syncthreads();

    int lane = t & 31, warp = t >> 5;
    int c_grp = lane & 15;          // 16 col groups of 8 cols
    int r_grp = lane >> 4;          // 2 row halves
    int c0 = c_grp * 8;
    int rbase = warp * 8 + r_grp * 4;

    ull acc2[4][4];                 // [row][col-pair]
#pragma unroll
    for (int r = 0; r < 4; r++)
#pragma unroll
        for (int p = 0; p < 4; p++) acc2[r][p] = 0ull;

    for (int k0 = 0; k0 < 128; k0 += 4) {
        float4 xr[4];
#pragma unroll
        for (int r = 0; r < 4; r++) xr[r] = *(const float4*)&xs[rbase + r][k0];
#pragma unroll
        for (int kk = 0; kk < 4; kk++) {
            const float* wrow = &W1[(k0 + kk) * 128 + c0];
            ulonglong2 wa = *(const ulonglong2*)wrow;        // pairs {c0,c0+1},{c0+2,c0+3}
            ulonglong2 wb = *(const ulonglong2*)(wrow + 4);  // pairs {c0+4..7}
#pragma unroll
            for (int r = 0; r < 4; r++) {
                float xv = ((const float*)&xr[r])[kk];
                ull xx = pack2(xv, xv);
                fma2(acc2[r][0], xx, wa.x);
                fma2(acc2[r][1], xx, wa.y);
                fma2(acc2[r][2], xx, wb.x);
                fma2(acc2[r][3], xx, wb.y);
            }
        }
    }

    // epilogue: store h1 + per-head attention dots
    float av_s[8], av_d[8];
#pragma unroll
    for (int i = 0; i < 8; i++) { av_s[i] = a_src[c0 + i]; av_d[i] = a_dst[c0 + i]; }
    int head = c_grp >> 2;

#pragma unroll
    for (int r = 0; r < 4; r++) {
        float ac[8];
#pragma unroll
        for (int p = 0; p < 4; p++) unpack2(acc2[r][p], ac[2 * p], ac[2 * p + 1]);
        int row = row0 + rbase + r;
        float ps = 0.f, pd = 0.f;
#pragma unroll
        for (int i = 0; i < 8; i++) { ps += ac[i] * av_s[i]; pd += ac[i] * av_d[i]; }
        // reduce across the 4 lanes sharing a head (consecutive lane ids)
        ps += __shfl_down_sync(0xffffffffu, ps, 2, 4);
        ps += __shfl_down_sync(0xffffffffu, ps, 1, 4);
        pd += __shfl_down_sync(0xffffffffu, pd, 2, 4);
        pd += __shfl_down_sync(0xffffffffu, pd, 1, 4);
        if (row < NN) {
            float* h1f = (float*)g_h1;
            *(float4*)&h1f[row * 128 + c0]     = make_float4(ac[0], ac[1], ac[2], ac[3]);
            *(float4*)&h1f[row * 128 + c0 + 4] = make_float4(ac[4], ac[5], ac[6], ac[7]);
            if ((c_grp & 3) == 0) {
                ((float*)&g_as1[row])[head] = ps;
                ((float*)&g_ad1[row])[head] = pd;
            }
        }
    }
}

// ---------------- CSR scan (shuffle-based) ----------------
__global__ void __launch_bounds__(1024) k_scanA() {
    __shared__ int wsum[32];
    int t = threadIdx.x, lane = t & 31, wid = t >> 5;
    int i = blockIdx.x * 1024 + t;
    int v = (i < NN) ? g_deg[i] : 0;
    int s = v;
#pragma unroll
    for (int o = 1; o < 32; o <<= 1) {
        int n = __shfl_up_sync(0xffffffffu, s, o);
        if (lane >= o) s += n;
    }
    if (lane == 31) wsum[wid] = s;
    __syncthreads();
    if (wid == 0) {
        int ws = wsum[lane];
#pragma unroll
        for (int o = 1; o < 32; o <<= 1) {
            int n = __shfl_up_sync(0xffffffffu, ws, o);
            if (lane >= o) ws += n;
        }
        wsum[lane] = ws;
    }
    __syncthreads();
    int res = s + (wid ? wsum[wid - 1] : 0);
    if (i < NN) g_incl[i] = res;
    if (t == 1023) g_bsum[blockIdx.x] = res;
}

__global__ void k_scanB() {   // 32 threads, NB=49 block sums
    int lane = threadIdx.x;
    int a = (lane < NB) ? g_bsum[lane] : 0;
#pragma unroll
    for (int o = 1; o < 32; o <<= 1) {
        int n = __shfl_up_sync(0xffffffffu, a, o);
        if (lane >= o) a += n;
    }
    int tot = __shfl_sync(0xffffffffu, a, 31);
    int b = (32 + lane < NB) ? g_bsum[32 + lane] : 0;
#pragma unroll
    for (int o = 1; o < 32; o <<= 1) {
        int n = __shfl_up_sync(0xffffffffu, b, o);
        if (lane >= o) b += n;
    }
    g_bscan[lane] = a;
    g_bscan[32 + lane] = b + tot;
}

__global__ void k_scanC() {
    int i = blockIdx.x * blockDim.x + threadIdx.x;
    if (i >= NN) return;
    int b = i >> 10;
    g_ptr[i] = g_incl[i] - g_deg[i] + (b ? g_bscan[b - 1] : 0);
}

__global__ void k_fill(const int* __restrict__ ei) {
    int e = blockIdx.x * blockDim.x + threadIdx.x;
    if (e >= ET) return;
    int s, d; edge_sd(ei, e, s, d);
    int pos = g_ptr[d] + atomicAdd(&g_cursor[d], 1);
    g_esrc[pos] = s;
}

// ---------------- layer-1 aggregation: one warp per dst node ----------------
__global__ void __launch_bounds__(256) k_agg1() {
    __shared__ int    s_src[8][32];
    __shared__ float4 s_al[8][32];
    int gw = (blockIdx.x * 256 + threadIdx.x) >> 5;
    if (gw >= NN) return;
    int lane = threadIdx.x & 31;
    int wb = threadIdx.x >> 5;

    int beg = g_ptr[gw], deg = g_deg[gw];
    float4 ad = g_ad1[gw];

    // pass 1: softmax denominator per head (no max-shift: |logit| small, exp safe)
    float4 ds = make_float4(0.f, 0.f, 0.f, 0.f);
    for (int base = 0; base < deg; base += 32) {
        int idx = base + lane;
        if (idx < deg) {
            int s = g_esrc[beg + idx];
            float4 a = g_as1[s];
            ds.x += __expf(lrelu(a.x + ad.x));
            ds.y += __expf(lrelu(a.y + ad.y));
            ds.z += __expf(lrelu(a.z + ad.z));
            ds.w += __expf(lrelu(a.w + ad.w));
        }
    }
#pragma unroll
    for (int o = 16; o; o >>= 1) {
        ds.x += __shfl_xor_sync(0xffffffffu, ds.x, o);
        ds.y += __shfl_xor_sync(0xffffffffu, ds.y, o);
        ds.z += __shfl_xor_sync(0xffffffffu, ds.z, o);
        ds.w += __shfl_xor_sync(0xffffffffu, ds.w, o);
    }
    float4 inv;
    inv.x = __fdividef(1.f, ds.x);
    inv.y = __fdividef(1.f, ds.y);
    inv.z = __fdividef(1.f, ds.z);
    inv.w = __fdividef(1.f, ds.w);

    // pass 2: accumulate h1[src] * alpha
    float4 acc = make_float4(0.f, 0.f, 0.f, 0.f);
    int head = lane >> 3;
    for (int base = 0; base < deg; base += 32) {
        int cnt = min(32, deg - base);
        if (lane < cnt) {
            int s = g_esrc[beg + base + lane];
            s_src[wb][lane] = s;
            float4 a = g_as1[s];
            float4 al;
            al.x = __expf(lrelu(a.x + ad.x)) * inv.x;
            al.y = __expf(lrelu(a.y + ad.y)) * inv.y;
            al.z = __expf(lrelu(a.z + ad.z)) * inv.z;
            al.w = __expf(lrelu(a.w + ad.w)) * inv.w;
            s_al[wb][lane] = al;
        }
        __syncwarp();
#pragma unroll 4
        for (int j = 0; j < cnt; j++) {
            int s = s_src[wb][j];
            float alpha = ((float*)&s_al[wb][j])[head];
            float4 h = g_h1[s * 32 + lane];
            acc.x += h.x * alpha;
            acc.y += h.y * alpha;
            acc.z += h.z * alpha;
            acc.w += h.w * alpha;
        }
        __syncwarp();
    }
    g_acc1[gw * 32 + lane] = acc;
}

// ---------------- GEMM2 (f32x2): relu(acc1+b1) @ [W2|ws|wd], 21 col-pairs ----------------
// 64 rows/block, thread = (col-pair, 4-row group): 21 * 16 = 336 threads.
__global__ void __launch_bounds__(336) k_gemm2(
    const float* __restrict__ W2, const float* __restrict__ b1)
{
    __shared__ float rs[64][128];   // 32KB
    int t = threadIdx.x;
    int row0 = blockIdx.x * 64;

    for (int i = t; i < 64 * 32; i += 336) {
        int r = i >> 5, kc = i & 31;
        int gr = min(row0 + r, NN - 1);
        float4 v = ((const float4*)(const float*)g_acc1)[gr * 32 + kc];
        float4 bv = ((const float4*)b1)[kc];
        rs[r][kc * 4 + 0] = fmaxf(v.x + bv.x, 0.f);
        rs[r][kc * 4 + 1] = fmaxf(v.y + bv.y, 0.f);
        rs[r][kc * 4 + 2] = fmaxf(v.z + bv.z, 0.f);
        rs[r][kc * 4 + 3] = fmaxf(v.w + bv.w, 0.f);
    }
    __syncthreads();

    int c_grp = t % 21;             // col-pair id: 0..19 -> W2 cols {2c,2c+1}, 20 -> {ws,wd}
    int r_grp = t / 21;             // 0..15
    int rbase = r_grp * 4;
    const float* wbase;
    int wstride;
    if (c_grp < 20) { wbase = W2 + c_grp * 2; wstride = OD; }
    else            { wbase = (const float*)g_wsd; wstride = 2; }

    ull acc2[4] = {0ull, 0ull, 0ull, 0ull};
    for (int k0 = 0; k0 < 128; k0 += 4) {
        float4 xr[4];
#pragma unroll
        for (int r = 0; r < 4; r++) xr[r] = *(const float4*)&rs[rbase + r][k0];
#pragma unroll
        for (int kk = 0; kk < 4; kk++) {
            ull wv = *(const ull*)&wbase[(k0 + kk) * wstride];
#pragma unroll
            for (int r = 0; r < 4; r++) {
                float xv = ((const float*)&xr[r])[kk];
                fma2(acc2[r], pack2(xv, xv), wv);
            }
        }
    }

    float* h2f = (float*)g_h2;
#pragma unroll
    for (int r = 0; r < 4; r++) {
        int row = row0 + rbase + r;
        if (row >= NN) continue;
        float lo, hi; unpack2(acc2[r], lo, hi);
        if (c_grp < 20) *(float2*)&h2f[row * OD + c_grp * 2] = make_float2(lo, hi);
        else            { g_as2[row] = lo; g_ad2[row] = hi; }
    }
}

// ---------------- layer-2 aggregation: one warp per dst node, 20 float2 lanes ----------------
__global__ void __launch_bounds__(256) k_agg2(float* __restrict__ out,
                                              const float* __restrict__ b2) {
    __shared__ int   s_src[8][32];
    __shared__ float s_al[8][32];
    int gw = (blockIdx.x * 256 + threadIdx.x) >> 5;
    if (gw >= NN) return;
    int lane = threadIdx.x & 31;
    int wb = threadIdx.x >> 5;

    int beg = g_ptr[gw], deg = g_deg[gw];
    float ad = g_ad2[gw];

    float ds = 0.f;
    for (int base = 0; base < deg; base += 32) {
        int idx = base + lane;
        if (idx < deg) ds += __expf(lrelu(g_as2[g_esrc[beg + idx]] + ad));
    }
#pragma unroll
    for (int o = 16; o; o >>= 1) ds += __shfl_xor_sync(0xffffffffu, ds, o);
    float inv = __fdividef(1.f, ds);

    const float2* h2f2 = (const float2*)g_h2;
    float2 acc = make_float2(0.f, 0.f);
    for (int base = 0; base < deg; base += 32) {
        int cnt = min(32, deg - base);
        if (lane < cnt) {
            int s = g_esrc[beg + base + lane];
            s_src[wb][lane] = s;
            s_al[wb][lane] = __expf(lrelu(g_as2[s] + ad)) * inv;
        }
        __syncwarp();
        if (lane < 20) {
#pragma unroll 4
            for (int j = 0; j < cnt; j++) {
                int s = s_src[wb][j];
                float alpha = s_al[wb][j];
                float2 h = h2f2[s * 20 + lane];
                acc.x += h.x * alpha;
                acc.y += h.y * alpha;
            }
        }
        __syncwarp();
    }
    if (lane < 20) {
        float2 bv = ((const float2*)b2)[lane];
        acc.x += bv.x; acc.y += bv.y;
        ((float2*)out)[gw * 20 + lane] = acc;
    }
}

// ---------------- launcher ----------------
extern "C" void kernel_launch(void* const* d_in, const int* in_sizes, int n_in,
                              void* d_out, int out_size)
{
    const float* x   = (const float*)d_in[0];
    const int*   ei  = (const int*)d_in[1];
    const float* W1  = (const float*)d_in[2];
    const float* as1 = (const float*)d_in[3];
    const float* ad1 = (const float*)d_in[4];
    const float* b1  = (const float*)d_in[5];
    const float* W2  = (const float*)d_in[6];
    const float* as2 = (const float*)d_in[7];
    const float* ad2 = (const float*)d_in[8];
    const float* b2  = (const float*)d_in[9];
    float* out = (float*)d_out;

    const int TB  = 256;
    const int EB  = (ET + TB - 1) / TB;
    const int NBK = (NN + TB - 1) / TB;
    const int WBK = (NN * 32 + TB - 1) / TB;

    k_zero_prep<<<NBK, TB>>>(W2, as2, ad2);
    k_gemm1<<<(NN + 63) / 64, 256>>>(x, W1, as1, ad1, ei);
    k_scanA<<<NB, 1024>>>();
    k_scanB<<<1, 32>>>();
    k_scanC<<<NBK, TB>>>();
    k_fill<<<EB, TB>>>(ei);
    k_agg1<<<WBK, TB>>>();
    k_gemm2<<<(NN + 63) / 64, 336>>>(W2, b1);
    k_agg2<<<WBK, TB>>>(out, b2);
}

// round 5
// speedup vs baseline: 1.0200x; 1.0200x over previous
#include <cuda_runtime.h>
#include <stdint.h>

#define NN    50000
#define NE    800000
#define ET    (NE + NN)      // 850000
#define OD    40
#define NEG_SLOPE 0.2f
#define NB    49             // ceil(NN/1024) scan blocks

// ---------------- scratch ----------------
__device__ float4 g_h1[NN * 32];      // [NN][128]
__device__ float4 g_acc1[NN * 32];    // [NN][128]
__device__ float4 g_as1[NN];
__device__ float4 g_ad1[NN];
__device__ float4 g_h2[NN * 10];      // [NN][40]
__device__ float  g_as2[NN];
__device__ float  g_ad2[NN];
__device__ float2 g_wsd[128];         // {W2@a2s, W2@a2d}[k]
// CSR
__device__ int    g_deg[NN];
__device__ int    g_incl[NN];
__device__ int    g_bsum[64];
__device__ int    g_ptr[NN];
__device__ int    g_eoff[ET];         // within-dst offset per edge
__device__ int    g_esrc[ET];

// ---------------- helpers ----------------
__device__ __forceinline__ float lrelu(float v) { return v > 0.f ? v : NEG_SLOPE * v; }

__device__ __forceinline__ void edge_sd(const int* __restrict__ ei, int e, int& s, int& d) {
    if (e < NE) { s = ei[e]; d = ei[NE + e]; }
    else        { s = d = e - NE; }
}

// ---------------- init: zero deg + fold a2s/a2d into extra W2 columns ----------------
__global__ void k_zero_prep(const float* __restrict__ W2,
                            const float* __restrict__ a2s, const float* __restrict__ a2d) {
    int i = blockIdx.x * blockDim.x + threadIdx.x;
    if (i < NN) g_deg[i] = 0;
    if (blockIdx.x == 0 && threadIdx.x < 128) {
        int k = threadIdx.x;
        float ws = 0.f, wd = 0.f;
#pragma unroll 8
        for (int c = 0; c < OD; c++) {
            float w = W2[k * OD + c];
            ws += w * a2s[c];
            wd += w * a2d[c];
        }
        g_wsd[k] = make_float2(ws, wd);
    }
}

// ---------------- GEMM1 (R3 shape) + fused degree histogram w/ offsets ----------------
__global__ void __launch_bounds__(256) k_gemm1(
    const float* __restrict__ x, const float* __restrict__ W1,
    const float* __restrict__ a_src, const float* __restrict__ a_dst,
    const int* __restrict__ ei)
{
    __shared__ float xs[32][128];
    int t = threadIdx.x;
    int lane = t & 31, warp = t >> 5;
    int row0 = blockIdx.x * 32;

    // fused histogram slice: also record within-node offset for atomic-free fill
    {
        const int S = (ET + gridDim.x - 1) / gridDim.x;
        int e0 = blockIdx.x * S;
        int e1 = min(ET, e0 + S);
        for (int e = e0 + t; e < e1; e += 256) {
            int d = (e < NE) ? ei[NE + e] : (e - NE);
            g_eoff[e] = atomicAdd(&g_deg[d], 1);
        }
    }

    for (int i = t; i < 32 * 32; i += 256) {
        int r = i >> 5, kc = i & 31;
        int gr = min(row0 + r, NN - 1);
        float4 v = ((const float4*)x)[gr * 32 + kc];
        *(float4*)&xs[r][kc * 4] = v;
    }
    __syncthreads();

    int c0 = lane * 4;
    int r0 = warp * 4;

    float acc[4][4];
#pragma unroll
    for (int r = 0; r < 4; r++)
#pragma unroll
        for (int c = 0; c < 4; c++) acc[r][c] = 0.f;

    for (int k = 0; k < 128; k += 4) {
        float4 w0 = *(const float4*)&W1[(k + 0) * 128 + c0];
        float4 w1 = *(const float4*)&W1[(k + 1) * 128 + c0];
        float4 w2 = *(const float4*)&W1[(k + 2) * 128 + c0];
        float4 w3 = *(const float4*)&W1[(k + 3) * 128 + c0];
#pragma unroll
        for (int r = 0; r < 4; r++) {
            float4 xr = *(const float4*)&xs[r0 + r][k];
            acc[r][0] += xr.x * w0.x; acc[r][1] += xr.x * w0.y; acc[r][2] += xr.x * w0.z; acc[r][3] += xr.x * w0.w;
            acc[r][0] += xr.y * w1.x; acc[r][1] += xr.y * w1.y; acc[r][2] += xr.y * w1.z; acc[r][3] += xr.y * w1.w;
            acc[r][0] += xr.z * w2.x; acc[r][1] += xr.z * w2.y; acc[r][2] += xr.z * w2.z; acc[r][3] += xr.z * w2.w;
            acc[r][0] += xr.w * w3.x; acc[r][1] += xr.w * w3.y; acc[r][2] += xr.w * w3.z; acc[r][3] += xr.w * w3.w;
        }
    }

    float as0 = a_src[c0], as1v = a_src[c0 + 1], as2v = a_src[c0 + 2], as3 = a_src[c0 + 3];
    float ad0 = a_dst[c0], ad1v = a_dst[c0 + 1], ad2v = a_dst[c0 + 2], ad3 = a_dst[c0 + 3];

#pragma unroll
    for (int r = 0; r < 4; r++) {
        int row = row0 + r0 + r;
        float ps = acc[r][0] * as0 + acc[r][1] * as1v + acc[r][2] * as2v + acc[r][3] * as3;
        float pd = acc[r][0] * ad0 + acc[r][1] * ad1v + acc[r][2] * ad2v + acc[r][3] * ad3;
#pragma unroll
        for (int o = 4; o; o >>= 1) {
            ps += __shfl_down_sync(0xffffffffu, ps, o, 8);
            pd += __shfl_down_sync(0xffffffffu, pd, o, 8);
        }
        if (row < NN) {
            g_h1[row * 32 + lane] = make_float4(acc[r][0], acc[r][1], acc[r][2], acc[r][3]);
            if ((lane & 7) == 0) {
                ((float*)&g_as1[row])[lane >> 3] = ps;
                ((float*)&g_ad1[row])[lane >> 3] = pd;
            }
        }
    }
}

// ---------------- CSR scan ----------------
__global__ void __launch_bounds__(1024) k_scanA() {
    __shared__ int wsum[32];
    int t = threadIdx.x, lane = t & 31, wid = t >> 5;
    int i = blockIdx.x * 1024 + t;
    int v = (i < NN) ? g_deg[i] : 0;
    int s = v;
#pragma unroll
    for (int o = 1; o < 32; o <<= 1) {
        int n = __shfl_up_sync(0xffffffffu, s, o);
        if (lane >= o) s += n;
    }
    if (lane == 31) wsum[wid] = s;
    __syncthreads();
    if (wid == 0) {
        int ws = wsum[lane];
#pragma unroll
        for (int o = 1; o < 32; o <<= 1) {
            int n = __shfl_up_sync(0xffffffffu, ws, o);
            if (lane >= o) ws += n;
        }
        wsum[lane] = ws;
    }
    __syncthreads();
    int res = s + (wid ? wsum[wid - 1] : 0);
    if (i < NN) g_incl[i] = res;
    if (t == 1023) g_bsum[blockIdx.x] = res;
}

// merged scanB+scanC: every block redundantly scans the 49 block sums (cheap),
// then converts inclusive->exclusive global offsets.
__global__ void __launch_bounds__(256) k_scanBC() {
    __shared__ int s_bscan[64];
    int t = threadIdx.x;
    if (t < 32) {
        int lane = t;
        int a = (lane < NB) ? g_bsum[lane] : 0;
#pragma unroll
        for (int o = 1; o < 32; o <<= 1) {
            int n = __shfl_up_sync(0xffffffffu, a, o);
            if (lane >= o) a += n;
        }
        int tot = __shfl_sync(0xffffffffu, a, 31);
        int b = (32 + lane < NB) ? g_bsum[32 + lane] : 0;
#pragma unroll
        for (int o = 1; o < 32; o <<= 1) {
            int n = __shfl_up_sync(0xffffffffu, b, o);
            if (lane >= o) b += n;
        }
        s_bscan[lane] = a;
        s_bscan[32 + lane] = b + tot;
    }
    __syncthreads();
    int i = blockIdx.x * 256 + t;
    if (i >= NN) return;
    int b = i >> 10;
    g_ptr[i] = g_incl[i] - g_deg[i] + (b ? s_bscan[b - 1] : 0);
}

// atomic-free fill: position = ptr[dst] + precomputed offset
__global__ void k_fill(const int* __restrict__ ei) {
    int e = blockIdx.x * blockDim.x + threadIdx.x;
    if (e >= ET) return;
    int s, d; edge_sd(ei, e, s, d);
    g_esrc[g_ptr[d] + g_eoff[e]] = s;
}

// ---------------- layer-1 aggregation: one warp per dst node ----------------
__global__ void __launch_bounds__(256) k_agg1() {
    __shared__ int    s_src[8][32];
    __shared__ float4 s_al[8][32];
    int gw = (blockIdx.x * 256 + threadIdx.x) >> 5;
    if (gw >= NN) return;
    int lane = threadIdx.x & 31;
    int wb = threadIdx.x >> 5;

    int beg = g_ptr[gw], deg = g_deg[gw];
    float4 ad = g_ad1[gw];

    // pass 1: softmax denominator per head (no max-shift: |logit| small, exp safe)
    float4 ds = make_float4(0.f, 0.f, 0.f, 0.f);
    for (int base = 0; base < deg; base += 32) {
        int idx = base + lane;
        if (idx < deg) {
            int s = g_esrc[beg + idx];
            float4 a = g_as1[s];
            ds.x += __expf(lrelu(a.x + ad.x));
            ds.y += __expf(lrelu(a.y + ad.y));
            ds.z += __expf(lrelu(a.z + ad.z));
            ds.w += __expf(lrelu(a.w + ad.w));
        }
    }
#pragma unroll
    for (int o = 16; o; o >>= 1) {
        ds.x += __shfl_xor_sync(0xffffffffu, ds.x, o);
        ds.y += __shfl_xor_sync(0xffffffffu, ds.y, o);
        ds.z += __shfl_xor_sync(0xffffffffu, ds.z, o);
        ds.w += __shfl_xor_sync(0xffffffffu, ds.w, o);
    }
    float4 inv;
    inv.x = __fdividef(1.f, ds.x);
    inv.y = __fdividef(1.f, ds.y);
    inv.z = __fdividef(1.f, ds.z);
    inv.w = __fdividef(1.f, ds.w);

    // pass 2: accumulate h1[src] * alpha
    float4 acc = make_float4(0.f, 0.f, 0.f, 0.f);
    int head = lane >> 3;
    for (int base = 0; base < deg; base += 32) {
        int cnt = min(32, deg - base);
        if (lane < cnt) {
            int s = g_esrc[beg + base + lane];
            s_src[wb][lane] = s;
            float4 a = g_as1[s];
            float4 al;
            al.x = __expf(lrelu(a.x + ad.x)) * inv.x;
            al.y = __expf(lrelu(a.y + ad.y)) * inv.y;
            al.z = __expf(lrelu(a.z + ad.z)) * inv.z;
            al.w = __expf(lrelu(a.w + ad.w)) * inv.w;
            s_al[wb][lane] = al;
        }
        __syncwarp();
#pragma unroll 4
        for (int j = 0; j < cnt; j++) {
            int s = s_src[wb][j];
            float alpha = ((float*)&s_al[wb][j])[head];
            float4 h = g_h1[s * 32 + lane];
            acc.x += h.x * alpha;
            acc.y += h.y * alpha;
            acc.z += h.z * alpha;
            acc.w += h.w * alpha;
        }
        __syncwarp();
    }
    g_acc1[gw * 32 + lane] = acc;
}

// ---------------- GEMM2 (R3 shape): relu(acc1+b1) @ [W2|ws|wd] ----------------
__global__ void __launch_bounds__(352) k_gemm2(
    const float* __restrict__ W2, const float* __restrict__ b1)
{
    __shared__ float rs[32][132];
    __shared__ float w2s[128][42];
    int t = threadIdx.x;
    int row0 = blockIdx.x * 32;

    for (int i = t; i < 32 * 32; i += 352) {
        int r = i >> 5, kc = i & 31;
        int gr = min(row0 + r, NN - 1);
        float4 v = ((const float4*)(const float*)g_acc1)[gr * 32 + kc];
        float4 bv = ((const float4*)b1)[kc];
        rs[r][kc * 4 + 0] = fmaxf(v.x + bv.x, 0.f);
        rs[r][kc * 4 + 1] = fmaxf(v.y + bv.y, 0.f);
        rs[r][kc * 4 + 2] = fmaxf(v.z + bv.z, 0.f);
        rs[r][kc * 4 + 3] = fmaxf(v.w + bv.w, 0.f);
    }
    for (int i = t; i < 128 * 42; i += 352) {
        int k = i / 42, c = i - k * 42;
        float v;
        if (c < OD)       v = W2[k * OD + c];
        else if (c == OD) v = g_wsd[k].x;
        else              v = g_wsd[k].y;
        w2s[k][c] = v;
    }
    __syncthreads();

    if (t < 336) {
        int c = t % 42, g = t / 42;
        int r0 = g * 4;
        float acc[4] = {0.f, 0.f, 0.f, 0.f};
        for (int k = 0; k < 128; k += 4) {
            float w0 = w2s[k][c], w1 = w2s[k + 1][c], w2v = w2s[k + 2][c], w3 = w2s[k + 3][c];
#pragma unroll
            for (int r = 0; r < 4; r++) {
                float4 xr = *(const float4*)&rs[r0 + r][k];
                acc[r] += xr.x * w0;
                acc[r] += xr.y * w1;
                acc[r] += xr.z * w2v;
                acc[r] += xr.w * w3;
            }
        }
#pragma unroll
        for (int r = 0; r < 4; r++) {
            int row = row0 + r0 + r;
            if (row < NN) {
                if (c < OD)       ((float*)g_h2)[row * OD + c] = acc[r];
                else if (c == OD) g_as2[row] = acc[r];
                else              g_ad2[row] = acc[r];
            }
        }
    }
}

// ---------------- layer-2 aggregation: one warp per dst node ----------------
__global__ void __launch_bounds__(256) k_agg2(float* __restrict__ out,
                                              const float* __restrict__ b2) {
    __shared__ int   s_src[8][32];
    __shared__ float s_al[8][32];
    int gw = (blockIdx.x * 256 + threadIdx.x) >> 5;
    if (gw >= NN) return;
    int lane = threadIdx.x & 31;
    int wb = threadIdx.x >> 5;

    int beg = g_ptr[gw], deg = g_deg[gw];
    float ad = g_ad2[gw];

    float ds = 0.f;
    for (int base = 0; base < deg; base += 32) {
        int idx = base + lane;
        if (idx < deg) ds += __expf(lrelu(g_as2[g_esrc[beg + idx]] + ad));
    }
#pragma unroll
    for (int o = 16; o; o >>= 1) ds += __shfl_xor_sync(0xffffffffu, ds, o);
    float inv = __fdividef(1.f, ds);

    const float2* h2f2 = (const float2*)g_h2;
    float2 acc = make_float2(0.f, 0.f);
    for (int base = 0; base < deg; base += 32) {
        int cnt = min(32, deg - base);
        if (lane < cnt) {
            int s = g_esrc[beg + base + lane];
            s_src[wb][lane] = s;
            s_al[wb][lane] = __expf(lrelu(g_as2[s] + ad)) * inv;
        }
        __syncwarp();
        if (lane < 20) {
#pragma unroll 4
            for (int j = 0; j < cnt; j++) {
                int s = s_src[wb][j];
                float alpha = s_al[wb][j];
                float2 h = h2f2[s * 20 + lane];
                acc.x += h.x * alpha;
                acc.y += h.y * alpha;
            }
        }
        __syncwarp();
    }
    if (lane < 20) {
        float2 bv = ((const float2*)b2)[lane];
        acc.x += bv.x; acc.y += bv.y;
        ((float2*)out)[gw * 20 + lane] = acc;
    }
}

// ---------------- launcher ----------------
extern "C" void kernel_launch(void* const* d_in, const int* in_sizes, int n_in,
                              void* d_out, int out_size)
{
    const float* x   = (const float*)d_in[0];
    const int*   ei  = (const int*)d_in[1];
    const float* W1  = (const float*)d_in[2];
    const float* as1 = (const float*)d_in[3];
    const float* ad1 = (const float*)d_in[4];
    const float* b1  = (const float*)d_in[5];
    const float* W2  = (const float*)d_in[6];
    const float* as2 = (const float*)d_in[7];
    const float* ad2 = (const float*)d_in[8];
    const float* b2  = (const float*)d_in[9];
    float* out = (float*)d_out;

    const int TB  = 256;
    const int EB  = (ET + TB - 1) / TB;
    const int NBK = (NN + TB - 1) / TB;
    const int WBK = (NN * 32 + TB - 1) / TB;

    k_zero_prep<<<NBK, TB>>>(W2, as2, ad2);
    k_gemm1<<<(NN + 31) / 32, 256>>>(x, W1, as1, ad1, ei);
    k_scanA<<<NB, 1024>>>();
    k_scanBC<<<NBK, TB>>>();
    k_fill<<<EB, TB>>>(ei);
    k_agg1<<<WBK, TB>>>();
    k_gemm2<<<(NN + 31) / 32, 352>>>(W2, b1);
    k_agg2<<<WBK, TB>>>(out, b2);
}

// round 6
// speedup vs baseline: 1.1260x; 1.1039x over previous
#include <cuda_runtime.h>
#include <cuda_fp16.h>
#include <stdint.h>

#define NN    50000
#define NE    800000
#define ET    (NE + NN)      // 850000
#define OD    40
#define NEG_SLOPE 0.2f
#define NB    49             // ceil(NN/1024) scan blocks

// ---------------- scratch ----------------
__device__ uint2  g_h1[NN * 32];      // [NN][128] as fp16 (4 halfs per uint2)
__device__ float4 g_acc1[NN * 32];    // [NN][128] fp32
__device__ float4 g_as1[NN];
__device__ float4 g_ad1[NN];
__device__ __half g_h2[NN * OD];      // [NN][40] fp16
__device__ float  g_as2[NN];
__device__ float  g_ad2[NN];
__device__ float2 g_wsd[128];         // {W2@a2s, W2@a2d}[k]
// CSR
__device__ int    g_deg[NN];
__device__ int    g_incl[NN];
__device__ int    g_bsum[64];
__device__ int    g_ptr[NN];
__device__ int    g_eoff[ET];
__device__ int    g_esrc[ET];

// ---------------- helpers ----------------
__device__ __forceinline__ float lrelu(float v) { return v > 0.f ? v : NEG_SLOPE * v; }

__device__ __forceinline__ void edge_sd(const int* __restrict__ ei, int e, int& s, int& d) {
    if (e < NE) { s = ei[e]; d = ei[NE + e]; }
    else        { s = d = e - NE; }
}

// ---------------- init: zero deg + fold a2s/a2d into extra W2 columns ----------------
__global__ void k_zero_prep(const float* __restrict__ W2,
                            const float* __restrict__ a2s, const float* __restrict__ a2d) {
    int i = blockIdx.x * blockDim.x + threadIdx.x;
    if (i < NN) g_deg[i] = 0;
    if (blockIdx.x == 0 && threadIdx.x < 128) {
        int k = threadIdx.x;
        float ws = 0.f, wd = 0.f;
#pragma unroll 8
        for (int c = 0; c < OD; c++) {
            float w = W2[k * OD + c];
            ws += w * a2s[c];
            wd += w * a2d[c];
        }
        g_wsd[k] = make_float2(ws, wd);
    }
}

// histogram + per-edge within-node offset (atomic returns the slot)
__global__ void k_hist(const int* __restrict__ ei) {
    int e = blockIdx.x * blockDim.x + threadIdx.x;
    if (e >= ET) return;
    int d = (e < NE) ? ei[NE + e] : (e - NE);
    g_eoff[e] = atomicAdd(&g_deg[d], 1);
}

// ---------------- GEMM1 (R3 shape, fp16 h1 output) ----------------
__global__ void __launch_bounds__(256) k_gemm1(
    const float* __restrict__ x, const float* __restrict__ W1,
    const float* __restrict__ a_src, const float* __restrict__ a_dst)
{
    __shared__ float xs[32][128];
    int t = threadIdx.x;
    int lane = t & 31, warp = t >> 5;
    int row0 = blockIdx.x * 32;

    for (int i = t; i < 32 * 32; i += 256) {
        int r = i >> 5, kc = i & 31;
        int gr = min(row0 + r, NN - 1);
        float4 v = ((const float4*)x)[gr * 32 + kc];
        *(float4*)&xs[r][kc * 4] = v;
    }
    __syncthreads();

    int c0 = lane * 4;
    int r0 = warp * 4;

    float acc[4][4];
#pragma unroll
    for (int r = 0; r < 4; r++)
#pragma unroll
        for (int c = 0; c < 4; c++) acc[r][c] = 0.f;

    for (int k = 0; k < 128; k += 4) {
        float4 w0 = *(const float4*)&W1[(k + 0) * 128 + c0];
        float4 w1 = *(const float4*)&W1[(k + 1) * 128 + c0];
        float4 w2 = *(const float4*)&W1[(k + 2) * 128 + c0];
        float4 w3 = *(const float4*)&W1[(k + 3) * 128 + c0];
#pragma unroll
        for (int r = 0; r < 4; r++) {
            float4 xr = *(const float4*)&xs[r0 + r][k];
            acc[r][0] += xr.x * w0.x; acc[r][1] += xr.x * w0.y; acc[r][2] += xr.x * w0.z; acc[r][3] += xr.x * w0.w;
            acc[r][0] += xr.y * w1.x; acc[r][1] += xr.y * w1.y; acc[r][2] += xr.y * w1.z; acc[r][3] += xr.y * w1.w;
            acc[r][0] += xr.z * w2.x; acc[r][1] += xr.z * w2.y; acc[r][2] += xr.z * w2.z; acc[r][3] += xr.z * w2.w;
            acc[r][0] += xr.w * w3.x; acc[r][1] += xr.w * w3.y; acc[r][2] += xr.w * w3.z; acc[r][3] += xr.w * w3.w;
        }
    }

    float as0 = a_src[c0], as1v = a_src[c0 + 1], as2v = a_src[c0 + 2], as3 = a_src[c0 + 3];
    float ad0 = a_dst[c0], ad1v = a_dst[c0 + 1], ad2v = a_dst[c0 + 2], ad3 = a_dst[c0 + 3];

#pragma unroll
    for (int r = 0; r < 4; r++) {
        int row = row0 + r0 + r;
        // attention dots from full-precision accumulators (logits stay fp32-exact)
        float ps = acc[r][0] * as0 + acc[r][1] * as1v + acc[r][2] * as2v + acc[r][3] * as3;
        float pd = acc[r][0] * ad0 + acc[r][1] * ad1v + acc[r][2] * ad2v + acc[r][3] * ad3;
#pragma unroll
        for (int o = 4; o; o >>= 1) {
            ps += __shfl_down_sync(0xffffffffu, ps, o, 8);
            pd += __shfl_down_sync(0xffffffffu, pd, o, 8);
        }
        if (row < NN) {
            __half2 h01 = __floats2half2_rn(acc[r][0], acc[r][1]);
            __half2 h23 = __floats2half2_rn(acc[r][2], acc[r][3]);
            uint2 hv;
            hv.x = *(unsigned*)&h01;
            hv.y = *(unsigned*)&h23;
            g_h1[row * 32 + lane] = hv;
            if ((lane & 7) == 0) {
                ((float*)&g_as1[row])[lane >> 3] = ps;
                ((float*)&g_ad1[row])[lane >> 3] = pd;
            }
        }
    }
}

// ---------------- CSR scan ----------------
__global__ void __launch_bounds__(1024) k_scanA() {
    __shared__ int wsum[32];
    int t = threadIdx.x, lane = t & 31, wid = t >> 5;
    int i = blockIdx.x * 1024 + t;
    int v = (i < NN) ? g_deg[i] : 0;
    int s = v;
#pragma unroll
    for (int o = 1; o < 32; o <<= 1) {
        int n = __shfl_up_sync(0xffffffffu, s, o);
        if (lane >= o) s += n;
    }
    if (lane == 31) wsum[wid] = s;
    __syncthreads();
    if (wid == 0) {
        int ws = wsum[lane];
#pragma unroll
        for (int o = 1; o < 32; o <<= 1) {
            int n = __shfl_up_sync(0xffffffffu, ws, o);
            if (lane >= o) ws += n;
        }
        wsum[lane] = ws;
    }
    __syncthreads();
    int res = s + (wid ? wsum[wid - 1] : 0);
    if (i < NN) g_incl[i] = res;
    if (t == 1023) g_bsum[blockIdx.x] = res;
}

__global__ void __launch_bounds__(256) k_scanBC() {
    __shared__ int s_bscan[64];
    int t = threadIdx.x;
    if (t < 32) {
        int lane = t;
        int a = (lane < NB) ? g_bsum[lane] : 0;
#pragma unroll
        for (int o = 1; o < 32; o <<= 1) {
            int n = __shfl_up_sync(0xffffffffu, a, o);
            if (lane >= o) a += n;
        }
        int tot = __shfl_sync(0xffffffffu, a, 31);
        int b = (32 + lane < NB) ? g_bsum[32 + lane] : 0;
#pragma unroll
        for (int o = 1; o < 32; o <<= 1) {
            int n = __shfl_up_sync(0xffffffffu, b, o);
            if (lane >= o) b += n;
        }
        s_bscan[lane] = a;
        s_bscan[32 + lane] = b + tot;
    }
    __syncthreads();
    int i = blockIdx.x * 256 + t;
    if (i >= NN) return;
    int b = i >> 10;
    g_ptr[i] = g_incl[i] - g_deg[i] + (b ? s_bscan[b - 1] : 0);
}

// atomic-free fill
__global__ void k_fill(const int* __restrict__ ei) {
    int e = blockIdx.x * blockDim.x + threadIdx.x;
    if (e >= ET) return;
    int s, d; edge_sd(ei, e, s, d);
    g_esrc[g_ptr[d] + g_eoff[e]] = s;
}

// ---------------- layer-1 aggregation: one warp per dst node (fp16 h1 gather) ----------------
__global__ void __launch_bounds__(256) k_agg1() {
    __shared__ int    s_src[8][32];
    __shared__ float4 s_al[8][32];
    int gw = (blockIdx.x * 256 + threadIdx.x) >> 5;
    if (gw >= NN) return;
    int lane = threadIdx.x & 31;
    int wb = threadIdx.x >> 5;

    int beg = g_ptr[gw], deg = g_deg[gw];
    float4 ad = g_ad1[gw];

    // pass 1: softmax denominator per head (no max-shift: |logit| small, exp safe)
    float4 ds = make_float4(0.f, 0.f, 0.f, 0.f);
    for (int base = 0; base < deg; base += 32) {
        int idx = base + lane;
        if (idx < deg) {
            int s = g_esrc[beg + idx];
            float4 a = g_as1[s];
            ds.x += __expf(lrelu(a.x + ad.x));
            ds.y += __expf(lrelu(a.y + ad.y));
            ds.z += __expf(lrelu(a.z + ad.z));
            ds.w += __expf(lrelu(a.w + ad.w));
        }
    }
#pragma unroll
    for (int o = 16; o; o >>= 1) {
        ds.x += __shfl_xor_sync(0xffffffffu, ds.x, o);
        ds.y += __shfl_xor_sync(0xffffffffu, ds.y, o);
        ds.z += __shfl_xor_sync(0xffffffffu, ds.z, o);
        ds.w += __shfl_xor_sync(0xffffffffu, ds.w, o);
    }
    float4 inv;
    inv.x = __fdividef(1.f, ds.x);
    inv.y = __fdividef(1.f, ds.y);
    inv.z = __fdividef(1.f, ds.z);
    inv.w = __fdividef(1.f, ds.w);

    // pass 2: accumulate h1[src] * alpha (fp16 gather, fp32 accumulate)
    float4 acc = make_float4(0.f, 0.f, 0.f, 0.f);
    int head = lane >> 3;
    for (int base = 0; base < deg; base += 32) {
        int cnt = min(32, deg - base);
        if (lane < cnt) {
            int s = g_esrc[beg + base + lane];
            s_src[wb][lane] = s;
            float4 a = g_as1[s];
            float4 al;
            al.x = __expf(lrelu(a.x + ad.x)) * inv.x;
            al.y = __expf(lrelu(a.y + ad.y)) * inv.y;
            al.z = __expf(lrelu(a.z + ad.z)) * inv.z;
            al.w = __expf(lrelu(a.w + ad.w)) * inv.w;
            s_al[wb][lane] = al;
        }
        __syncwarp();
#pragma unroll 4
        for (int j = 0; j < cnt; j++) {
            int s = s_src[wb][j];
            float alpha = ((float*)&s_al[wb][j])[head];
            uint2 hv = g_h1[s * 32 + lane];
            float2 lo = __half22float2(*(__half2*)&hv.x);
            float2 hi = __half22float2(*(__half2*)&hv.y);
            acc.x += lo.x * alpha;
            acc.y += lo.y * alpha;
            acc.z += hi.x * alpha;
            acc.w += hi.y * alpha;
        }
        __syncwarp();
    }
    g_acc1[gw * 32 + lane] = acc;
}

// ---------------- GEMM2 (R3 shape, fp16 h2 output) ----------------
__global__ void __launch_bounds__(352) k_gemm2(
    const float* __restrict__ W2, const float* __restrict__ b1)
{
    __shared__ float rs[32][132];
    __shared__ float w2s[128][42];
    int t = threadIdx.x;
    int row0 = blockIdx.x * 32;

    for (int i = t; i < 32 * 32; i += 352) {
        int r = i >> 5, kc = i & 31;
        int gr = min(row0 + r, NN - 1);
        float4 v = ((const float4*)(const float*)g_acc1)[gr * 32 + kc];
        float4 bv = ((const float4*)b1)[kc];
        rs[r][kc * 4 + 0] = fmaxf(v.x + bv.x, 0.f);
        rs[r][kc * 4 + 1] = fmaxf(v.y + bv.y, 0.f);
        rs[r][kc * 4 + 2] = fmaxf(v.z + bv.z, 0.f);
        rs[r][kc * 4 + 3] = fmaxf(v.w + bv.w, 0.f);
    }
    for (int i = t; i < 128 * 42; i += 352) {
        int k = i / 42, c = i - k * 42;
        float v;
        if (c < OD)       v = W2[k * OD + c];
        else if (c == OD) v = g_wsd[k].x;
        else              v = g_wsd[k].y;
        w2s[k][c] = v;
    }
    __syncthreads();

    if (t < 336) {
        int c = t % 42, g = t / 42;
        int r0 = g * 4;
        float acc[4] = {0.f, 0.f, 0.f, 0.f};
        for (int k = 0; k < 128; k += 4) {
            float w0 = w2s[k][c], w1 = w2s[k + 1][c], w2v = w2s[k + 2][c], w3 = w2s[k + 3][c];
#pragma unroll
            for (int r = 0; r < 4; r++) {
                float4 xr = *(const float4*)&rs[r0 + r][k];
                acc[r] += xr.x * w0;
                acc[r] += xr.y * w1;
                acc[r] += xr.z * w2v;
                acc[r] += xr.w * w3;
            }
        }
#pragma unroll
        for (int r = 0; r < 4; r++) {
            int row = row0 + r0 + r;
            if (row < NN) {
                if (c < OD)       g_h2[row * OD + c] = __float2half_rn(acc[r]);
                else if (c == OD) g_as2[row] = acc[r];
                else              g_ad2[row] = acc[r];
            }
        }
    }
}

// ---------------- layer-2 aggregation: one warp per dst node (fp16 h2 gather) ----------------
__global__ void __launch_bounds__(256) k_agg2(float* __restrict__ out,
                                              const float* __restrict__ b2) {
    __shared__ int   s_src[8][32];
    __shared__ float s_al[8][32];
    int gw = (blockIdx.x * 256 + threadIdx.x) >> 5;
    if (gw >= NN) return;
    int lane = threadIdx.x & 31;
    int wb = threadIdx.x >> 5;

    int beg = g_ptr[gw], deg = g_deg[gw];
    float ad = g_ad2[gw];

    float ds = 0.f;
    for (int base = 0; base < deg; base += 32) {
        int idx = base + lane;
        if (idx < deg) ds += __expf(lrelu(g_as2[g_esrc[beg + idx]] + ad));
    }
#pragma unroll
    for (int o = 16; o; o >>= 1) ds += __shfl_xor_sync(0xffffffffu, ds, o);
    float inv = __fdividef(1.f, ds);

    const __half2* h2p = (const __half2*)g_h2;   // [NN][20] half2
    float2 acc = make_float2(0.f, 0.f);
    for (int base = 0; base < deg; base += 32) {
        int cnt = min(32, deg - base);
        if (lane < cnt) {
            int s = g_esrc[beg + base + lane];
            s_src[wb][lane] = s;
            s_al[wb][lane] = __expf(lrelu(g_as2[s] + ad)) * inv;
        }
        __syncwarp();
        if (lane < 20) {
#pragma unroll 4
            for (int j = 0; j < cnt; j++) {
                int s = s_src[wb][j];
                float alpha = s_al[wb][j];
                float2 h = __half22float2(h2p[s * 20 + lane]);
                acc.x += h.x * alpha;
                acc.y += h.y * alpha;
            }
        }
        __syncwarp();
    }
    if (lane < 20) {
        float2 bv = ((const float2*)b2)[lane];
        acc.x += bv.x; acc.y += bv.y;
        ((float2*)out)[gw * 20 + lane] = acc;
    }
}

// ---------------- launcher ----------------
extern "C" void kernel_launch(void* const* d_in, const int* in_sizes, int n_in,
                              void* d_out, int out_size)
{
    const float* x   = (const float*)d_in[0];
    const int*   ei  = (const int*)d_in[1];
    const float* W1  = (const float*)d_in[2];
    const float* as1 = (const float*)d_in[3];
    const float* ad1 = (const float*)d_in[4];
    const float* b1  = (const float*)d_in[5];
    const float* W2  = (const float*)d_in[6];
    const float* as2 = (const float*)d_in[7];
    const float* ad2 = (const float*)d_in[8];
    const float* b2  = (const float*)d_in[9];
    float* out = (float*)d_out;

    const int TB  = 256;
    const int EB  = (ET + TB - 1) / TB;
    const int NBK = (NN + TB - 1) / TB;
    const int WBK = (NN * 32 + TB - 1) / TB;

    k_zero_prep<<<NBK, TB>>>(W2, as2, ad2);
    k_hist<<<EB, TB>>>(ei);
    k_gemm1<<<(NN + 31) / 32, 256>>>(x, W1, as1, ad1);
    k_scanA<<<NB, 1024>>>();
    k_scanBC<<<NBK, TB>>>();
    k_fill<<<EB, TB>>>(ei);
    k_agg1<<<WBK, TB>>>();
    k_gemm2<<<(NN + 31) / 32, 352>>>(W2, b1);
    k_agg2<<<WBK, TB>>>(out, b2);
}

// round 7
// speedup vs baseline: 1.1575x; 1.0280x over previous
#include <cuda_runtime.h>
#include <cuda_fp16.h>
#include <stdint.h>

#define NN    50000
#define NE    800000
#define ET    (NE + NN)      // 850000
#define OD    40
#define NEG_SLOPE 0.2f
#define NB    49             // ceil(NN/1024) scan blocks

// ---------------- scratch ----------------
__device__ uint2  g_h1[NN * 32];      // [NN][128] as fp16 (4 halfs per uint2)
__device__ float4 g_acc1[NN * 32];    // [NN][128] fp32
__device__ float4 g_as1[NN];
__device__ float4 g_ad1[NN];
__device__ __half g_h2[NN * OD];      // [NN][40] fp16
__device__ float  g_as2[NN];
__device__ float  g_ad2[NN];
__device__ float2 g_wsd[128];         // {W2@a2s, W2@a2d}[k]
// CSR
__device__ int    g_deg[NN];
__device__ int    g_incl[NN];
__device__ int    g_bsum[64];
__device__ int    g_ptr[NN];
__device__ int    g_eoff[ET];
__device__ int    g_esrc[ET];

// ---------------- helpers ----------------
__device__ __forceinline__ float lrelu(float v) { return v > 0.f ? v : NEG_SLOPE * v; }

__device__ __forceinline__ void edge_sd(const int* __restrict__ ei, int e, int& s, int& d) {
    if (e < NE) { s = ei[e]; d = ei[NE + e]; }
    else        { s = d = e - NE; }
}

// ---------------- init: zero deg + fold a2s/a2d into extra W2 columns ----------------
__global__ void k_zero_prep(const float* __restrict__ W2,
                            const float* __restrict__ a2s, const float* __restrict__ a2d) {
    int i = blockIdx.x * blockDim.x + threadIdx.x;
    if (i < NN) g_deg[i] = 0;
    if (blockIdx.x == 0 && threadIdx.x < 128) {
        int k = threadIdx.x;
        float ws = 0.f, wd = 0.f;
#pragma unroll 8
        for (int c = 0; c < OD; c++) {
            float w = W2[k * OD + c];
            ws += w * a2s[c];
            wd += w * a2d[c];
        }
        g_wsd[k] = make_float2(ws, wd);
    }
}

// histogram + per-edge within-node offset (atomic returns the slot)
__global__ void k_hist(const int* __restrict__ ei) {
    int e = blockIdx.x * blockDim.x + threadIdx.x;
    if (e >= ET) return;
    int d = (e < NE) ? ei[NE + e] : (e - NE);
    g_eoff[e] = atomicAdd(&g_deg[d], 1);
}

// ---------------- GEMM1 (fp16 h1 output, fp32 logits) ----------------
__global__ void __launch_bounds__(256) k_gemm1(
    const float* __restrict__ x, const float* __restrict__ W1,
    const float* __restrict__ a_src, const float* __restrict__ a_dst)
{
    __shared__ float xs[32][128];
    int t = threadIdx.x;
    int lane = t & 31, warp = t >> 5;
    int row0 = blockIdx.x * 32;

    for (int i = t; i < 32 * 32; i += 256) {
        int r = i >> 5, kc = i & 31;
        int gr = min(row0 + r, NN - 1);
        float4 v = ((const float4*)x)[gr * 32 + kc];
        *(float4*)&xs[r][kc * 4] = v;
    }
    __syncthreads();

    int c0 = lane * 4;
    int r0 = warp * 4;

    float acc[4][4];
#pragma unroll
    for (int r = 0; r < 4; r++)
#pragma unroll
        for (int c = 0; c < 4; c++) acc[r][c] = 0.f;

    for (int k = 0; k < 128; k += 4) {
        float4 w0 = *(const float4*)&W1[(k + 0) * 128 + c0];
        float4 w1 = *(const float4*)&W1[(k + 1) * 128 + c0];
        float4 w2 = *(const float4*)&W1[(k + 2) * 128 + c0];
        float4 w3 = *(const float4*)&W1[(k + 3) * 128 + c0];
#pragma unroll
        for (int r = 0; r < 4; r++) {
            float4 xr = *(const float4*)&xs[r0 + r][k];
            acc[r][0] += xr.x * w0.x; acc[r][1] += xr.x * w0.y; acc[r][2] += xr.x * w0.z; acc[r][3] += xr.x * w0.w;
            acc[r][0] += xr.y * w1.x; acc[r][1] += xr.y * w1.y; acc[r][2] += xr.y * w1.z; acc[r][3] += xr.y * w1.w;
            acc[r][0] += xr.z * w2.x; acc[r][1] += xr.z * w2.y; acc[r][2] += xr.z * w2.z; acc[r][3] += xr.z * w2.w;
            acc[r][0] += xr.w * w3.x; acc[r][1] += xr.w * w3.y; acc[r][2] += xr.w * w3.z; acc[r][3] += xr.w * w3.w;
        }
    }

    float as0 = a_src[c0], as1v = a_src[c0 + 1], as2v = a_src[c0 + 2], as3 = a_src[c0 + 3];
    float ad0 = a_dst[c0], ad1v = a_dst[c0 + 1], ad2v = a_dst[c0 + 2], ad3 = a_dst[c0 + 3];

#pragma unroll
    for (int r = 0; r < 4; r++) {
        int row = row0 + r0 + r;
        float ps = acc[r][0] * as0 + acc[r][1] * as1v + acc[r][2] * as2v + acc[r][3] * as3;
        float pd = acc[r][0] * ad0 + acc[r][1] * ad1v + acc[r][2] * ad2v + acc[r][3] * ad3;
#pragma unroll
        for (int o = 4; o; o >>= 1) {
            ps += __shfl_down_sync(0xffffffffu, ps, o, 8);
            pd += __shfl_down_sync(0xffffffffu, pd, o, 8);
        }
        if (row < NN) {
            __half2 h01 = __floats2half2_rn(acc[r][0], acc[r][1]);
            __half2 h23 = __floats2half2_rn(acc[r][2], acc[r][3]);
            uint2 hv;
            hv.x = *(unsigned*)&h01;
            hv.y = *(unsigned*)&h23;
            g_h1[row * 32 + lane] = hv;
            if ((lane & 7) == 0) {
                ((float*)&g_as1[row])[lane >> 3] = ps;
                ((float*)&g_ad1[row])[lane >> 3] = pd;
            }
        }
    }
}

// ---------------- CSR scan ----------------
__global__ void __launch_bounds__(1024) k_scanA() {
    __shared__ int wsum[32];
    int t = threadIdx.x, lane = t & 31, wid = t >> 5;
    int i = blockIdx.x * 1024 + t;
    int v = (i < NN) ? g_deg[i] : 0;
    int s = v;
#pragma unroll
    for (int o = 1; o < 32; o <<= 1) {
        int n = __shfl_up_sync(0xffffffffu, s, o);
        if (lane >= o) s += n;
    }
    if (lane == 31) wsum[wid] = s;
    __syncthreads();
    if (wid == 0) {
        int ws = wsum[lane];
#pragma unroll
        for (int o = 1; o < 32; o <<= 1) {
            int n = __shfl_up_sync(0xffffffffu, ws, o);
            if (lane >= o) ws += n;
        }
        wsum[lane] = ws;
    }
    __syncthreads();
    int res = s + (wid ? wsum[wid - 1] : 0);
    if (i < NN) g_incl[i] = res;
    if (t == 1023) g_bsum[blockIdx.x] = res;
}

__global__ void __launch_bounds__(256) k_scanBC() {
    __shared__ int s_bscan[64];
    int t = threadIdx.x;
    if (t < 32) {
        int lane = t;
        int a = (lane < NB) ? g_bsum[lane] : 0;
#pragma unroll
        for (int o = 1; o < 32; o <<= 1) {
            int n = __shfl_up_sync(0xffffffffu, a, o);
            if (lane >= o) a += n;
        }
        int tot = __shfl_sync(0xffffffffu, a, 31);
        int b = (32 + lane < NB) ? g_bsum[32 + lane] : 0;
#pragma unroll
        for (int o = 1; o < 32; o <<= 1) {
            int n = __shfl_up_sync(0xffffffffu, b, o);
            if (lane >= o) b += n;
        }
        s_bscan[lane] = a;
        s_bscan[32 + lane] = b + tot;
    }
    __syncthreads();
    int i = blockIdx.x * 256 + t;
    if (i >= NN) return;
    int b = i >> 10;
    g_ptr[i] = g_incl[i] - g_deg[i] + (b ? s_bscan[b - 1] : 0);
}

// atomic-free fill
__global__ void k_fill(const int* __restrict__ ei) {
    int e = blockIdx.x * blockDim.x + threadIdx.x;
    if (e >= ET) return;
    int s, d; edge_sd(ei, e, s, d);
    g_esrc[g_ptr[d] + g_eoff[e]] = s;
}

// ---------------- layer-1 aggregation: SINGLE PASS, one warp per dst node ----------------
// out = (sum_j exp(l_j) * h_j) / (sum_j exp(l_j)) -- normalize once at the end.
__global__ void __launch_bounds__(256) k_agg1() {
    __shared__ int    s_src[8][32];
    __shared__ float4 s_al[8][32];
    int gw = (blockIdx.x * 256 + threadIdx.x) >> 5;
    if (gw >= NN) return;
    int lane = threadIdx.x & 31;
    int wb = threadIdx.x >> 5;

    int beg = g_ptr[gw], deg = g_deg[gw];
    float4 ad = g_ad1[gw];

    float4 acc = make_float4(0.f, 0.f, 0.f, 0.f);   // unnormalized message (4 ch of one head)
    float4 dsl = make_float4(0.f, 0.f, 0.f, 0.f);   // per-lane partial denominators (per head)
    int head = lane >> 3;

    for (int base = 0; base < deg; base += 32) {
        int cnt = min(32, deg - base);
        if (lane < cnt) {
            int s = g_esrc[beg + base + lane];
            s_src[wb][lane] = s;
            float4 a = g_as1[s];
            float4 ev;
            ev.x = __expf(lrelu(a.x + ad.x));
            ev.y = __expf(lrelu(a.y + ad.y));
            ev.z = __expf(lrelu(a.z + ad.z));
            ev.w = __expf(lrelu(a.w + ad.w));
            s_al[wb][lane] = ev;
            dsl.x += ev.x; dsl.y += ev.y; dsl.z += ev.z; dsl.w += ev.w;
        }
        __syncwarp();
#pragma unroll 4
        for (int j = 0; j < cnt; j++) {
            int s = s_src[wb][j];
            float ev = ((float*)&s_al[wb][j])[head];
            uint2 hv = g_h1[s * 32 + lane];
            float2 lo = __half22float2(*(__half2*)&hv.x);
            float2 hi = __half22float2(*(__half2*)&hv.y);
            acc.x += lo.x * ev;
            acc.y += lo.y * ev;
            acc.z += hi.x * ev;
            acc.w += hi.y * ev;
        }
        __syncwarp();
    }

    // reduce denominators across the warp (components = heads), then scale once
#pragma unroll
    for (int o = 16; o; o >>= 1) {
        dsl.x += __shfl_xor_sync(0xffffffffu, dsl.x, o);
        dsl.y += __shfl_xor_sync(0xffffffffu, dsl.y, o);
        dsl.z += __shfl_xor_sync(0xffffffffu, dsl.z, o);
        dsl.w += __shfl_xor_sync(0xffffffffu, dsl.w, o);
    }
    float invh = __fdividef(1.f, ((float*)&dsl)[head]);
    acc.x *= invh; acc.y *= invh; acc.z *= invh; acc.w *= invh;
    g_acc1[gw * 32 + lane] = acc;
}

// ---------------- GEMM2 (fp16 h2 output) ----------------
__global__ void __launch_bounds__(352) k_gemm2(
    const float* __restrict__ W2, const float* __restrict__ b1)
{
    __shared__ float rs[32][132];
    __shared__ float w2s[128][42];
    int t = threadIdx.x;
    int row0 = blockIdx.x * 32;

    for (int i = t; i < 32 * 32; i += 352) {
        int r = i >> 5, kc = i & 31;
        int gr = min(row0 + r, NN - 1);
        float4 v = ((const float4*)(const float*)g_acc1)[gr * 32 + kc];
        float4 bv = ((const float4*)b1)[kc];
        rs[r][kc * 4 + 0] = fmaxf(v.x + bv.x, 0.f);
        rs[r][kc * 4 + 1] = fmaxf(v.y + bv.y, 0.f);
        rs[r][kc * 4 + 2] = fmaxf(v.z + bv.z, 0.f);
        rs[r][kc * 4 + 3] = fmaxf(v.w + bv.w, 0.f);
    }
    for (int i = t; i < 128 * 42; i += 352) {
        int k = i / 42, c = i - k * 42;
        float v;
        if (c < OD)       v = W2[k * OD + c];
        else if (c == OD) v = g_wsd[k].x;
        else              v = g_wsd[k].y;
        w2s[k][c] = v;
    }
    __syncthreads();

    if (t < 336) {
        int c = t % 42, g = t / 42;
        int r0 = g * 4;
        float acc[4] = {0.f, 0.f, 0.f, 0.f};
        for (int k = 0; k < 128; k += 4) {
            float w0 = w2s[k][c], w1 = w2s[k + 1][c], w2v = w2s[k + 2][c], w3 = w2s[k + 3][c];
#pragma unroll
            for (int r = 0; r < 4; r++) {
                float4 xr = *(const float4*)&rs[r0 + r][k];
                acc[r] += xr.x * w0;
                acc[r] += xr.y * w1;
                acc[r] += xr.z * w2v;
                acc[r] += xr.w * w3;
            }
        }
#pragma unroll
        for (int r = 0; r < 4; r++) {
            int row = row0 + r0 + r;
            if (row < NN) {
                if (c < OD)       g_h2[row * OD + c] = __float2half_rn(acc[r]);
                else if (c == OD) g_as2[row] = acc[r];
                else              g_ad2[row] = acc[r];
            }
        }
    }
}

// ---------------- layer-2 aggregation: SINGLE PASS, one warp per dst node ----------------
__global__ void __launch_bounds__(256) k_agg2(float* __restrict__ out,
                                              const float* __restrict__ b2) {
    __shared__ int   s_src[8][32];
    __shared__ float s_al[8][32];
    int gw = (blockIdx.x * 256 + threadIdx.x) >> 5;
    if (gw >= NN) return;
    int lane = threadIdx.x & 31;
    int wb = threadIdx.x >> 5;

    int beg = g_ptr[gw], deg = g_deg[gw];
    float ad = g_ad2[gw];

    const __half2* h2p = (const __half2*)g_h2;   // [NN][20] half2
    float2 acc = make_float2(0.f, 0.f);
    float dsl = 0.f;

    for (int base = 0; base < deg; base += 32) {
        int cnt = min(32, deg - base);
        if (lane < cnt) {
            int s = g_esrc[beg + base + lane];
            s_src[wb][lane] = s;
            float ev = __expf(lrelu(g_as2[s] + ad));
            s_al[wb][lane] = ev;
            dsl += ev;
        }
        __syncwarp();
        if (lane < 20) {
#pragma unroll 4
            for (int j = 0; j < cnt; j++) {
                int s = s_src[wb][j];
                float ev = s_al[wb][j];
                float2 h = __half22float2(h2p[s * 20 + lane]);
                acc.x += h.x * ev;
                acc.y += h.y * ev;
            }
        }
        __syncwarp();
    }

#pragma unroll
    for (int o = 16; o; o >>= 1) dsl += __shfl_xor_sync(0xffffffffu, dsl, o);
    float inv = __fdividef(1.f, dsl);

    if (lane < 20) {
        float2 bv = ((const float2*)b2)[lane];
        acc.x = acc.x * inv + bv.x;
        acc.y = acc.y * inv + bv.y;
        ((float2*)out)[gw * 20 + lane] = acc;
    }
}

// ---------------- launcher ----------------
extern "C" void kernel_launch(void* const* d_in, const int* in_sizes, int n_in,
                              void* d_out, int out_size)
{
    const float* x   = (const float*)d_in[0];
    const int*   ei  = (const int*)d_in[1];
    const float* W1  = (const float*)d_in[2];
    const float* as1 = (const float*)d_in[3];
    const float* ad1 = (const float*)d_in[4];
    const float* b1  = (const float*)d_in[5];
    const float* W2  = (const float*)d_in[6];
    const float* as2 = (const float*)d_in[7];
    const float* ad2 = (const float*)d_in[8];
    const float* b2  = (const float*)d_in[9];
    float* out = (float*)d_out;

    const int TB  = 256;
    const int EB  = (ET + TB - 1) / TB;
    const int NBK = (NN + TB - 1) / TB;
    const int WBK = (NN * 32 + TB - 1) / TB;

    k_zero_prep<<<NBK, TB>>>(W2, as2, ad2);
    k_hist<<<EB, TB>>>(ei);
    k_gemm1<<<(NN + 31) / 32, 256>>>(x, W1, as1, ad1);
    k_scanA<<<NB, 1024>>>();
    k_scanBC<<<NBK, TB>>>();
    k_fill<<<EB, TB>>>(ei);
    k_agg1<<<WBK, TB>>>();
    k_gemm2<<<(NN + 31) / 32, 352>>>(W2, b1);
    k_agg2<<<WBK, TB>>>(out, b2);
}

// round 8
// speedup vs baseline: 1.3326x; 1.1512x over previous
#include <cuda_runtime.h>
#include <cuda_fp16.h>
#include <stdint.h>

#define NN    50000
#define NE    800000
#define ET    (NE + NN)      // 850000
#define OD    40
#define NEG_SLOPE 0.2f
#define NB    49             // ceil(NN/1024) scan blocks

#define LDA 136              // A smem row stride (halfs): 17x16B -> ldmatrix conflict-free
#define LDB 152              // B smem row stride (halfs): 19x16B -> conflict-free

// ---------------- scratch ----------------
__device__ __align__(16) __half g_W1h[128 * 144];  // [W1 | Va | Vd | pad] fp16
__device__ uint2  g_h1[NN * 32];      // [NN][128] fp16
__device__ float4 g_acc1[NN * 32];    // [NN][128] fp32
__device__ float4 g_as1[NN];
__device__ float4 g_ad1[NN];
__device__ __half g_h2[NN * OD];      // [NN][40] fp16
__device__ float  g_as2[NN];
__device__ float  g_ad2[NN];
__device__ float2 g_wsd[128];         // {W2@a2s, W2@a2d}[k]
// CSR
__device__ int    g_deg[NN];
__device__ int    g_incl[NN];
__device__ int    g_bsum[64];
__device__ int    g_ptr[NN];
__device__ int    g_eoff[ET];
__device__ int    g_esrc[ET];

// ---------------- helpers ----------------
__device__ __forceinline__ float lrelu(float v) { return v > 0.f ? v : NEG_SLOPE * v; }

__device__ __forceinline__ void edge_sd(const int* __restrict__ ei, int e, int& s, int& d) {
    if (e < NE) { s = ei[e]; d = ei[NE + e]; }
    else        { s = d = e - NE; }
}

__device__ __forceinline__ uint32_t smem_u32(const void* p) {
    return (uint32_t)__cvta_generic_to_shared(p);
}

__device__ __forceinline__ void ldmatrix_x4(uint32_t& r0, uint32_t& r1, uint32_t& r2, uint32_t& r3, uint32_t addr) {
    asm volatile("ldmatrix.sync.aligned.m8n8.x4.shared.b16 {%0,%1,%2,%3}, [%4];"
                 : "=r"(r0), "=r"(r1), "=r"(r2), "=r"(r3) : "r"(addr));
}
__device__ __forceinline__ void ldmatrix_x4_trans(uint32_t& r0, uint32_t& r1, uint32_t& r2, uint32_t& r3, uint32_t addr) {
    asm volatile("ldmatrix.sync.aligned.m8n8.x4.trans.shared.b16 {%0,%1,%2,%3}, [%4];"
                 : "=r"(r0), "=r"(r1), "=r"(r2), "=r"(r3) : "r"(addr));
}
__device__ __forceinline__ void mma16816(float* d, uint32_t a0, uint32_t a1, uint32_t a2, uint32_t a3,
                                         uint32_t b0, uint32_t b1) {
    asm volatile("mma.sync.aligned.m16n8k16.row.col.f32.f16.f16.f32 "
                 "{%0,%1,%2,%3}, {%4,%5,%6,%7}, {%8,%9}, {%0,%1,%2,%3};"
                 : "+f"(d[0]), "+f"(d[1]), "+f"(d[2]), "+f"(d[3])
                 : "r"(a0), "r"(a1), "r"(a2), "r"(a3), "r"(b0), "r"(b1));
}

// ---------------- init: zero deg + build W1h (with folded attn cols) + wsd ----------------
__global__ void k_zero_prep(const float* __restrict__ W1,
                            const float* __restrict__ a1s, const float* __restrict__ a1d,
                            const float* __restrict__ W2,
                            const float* __restrict__ a2s, const float* __restrict__ a2d) {
    int i = blockIdx.x * blockDim.x + threadIdx.x;
    if (i < NN) g_deg[i] = 0;
    if (blockIdx.x == 0 && threadIdx.x < 128) {
        int k = threadIdx.x;
        float ws = 0.f, wd = 0.f;
#pragma unroll 8
        for (int c = 0; c < OD; c++) {
            float w = W2[k * OD + c];
            ws += w * a2s[c];
            wd += w * a2d[c];
        }
        g_wsd[k] = make_float2(ws, wd);
    }
    if (blockIdx.x == 1 && threadIdx.x < 128) {
        int k = threadIdx.x;
        __half* dst = &g_W1h[k * 144];
        float va[4] = {0.f, 0.f, 0.f, 0.f}, vd[4] = {0.f, 0.f, 0.f, 0.f};
        for (int c = 0; c < 128; c++) {
            float w = W1[k * 128 + c];
            dst[c] = __float2half_rn(w);
            int h = c >> 5;
            va[h] += w * a1s[c];
            vd[h] += w * a1d[c];
        }
#pragma unroll
        for (int h = 0; h < 4; h++) {
            dst[128 + h] = __float2half_rn(va[h]);
            dst[132 + h] = __float2half_rn(vd[h]);
        }
#pragma unroll
        for (int c = 136; c < 144; c++) dst[c] = __float2half_rn(0.f);
    }
}

// histogram + per-edge within-node offset
__global__ void k_hist(const int* __restrict__ ei) {
    int e = blockIdx.x * blockDim.x + threadIdx.x;
    if (e >= ET) return;
    int d = (e < NE) ? ei[NE + e] : (e - NE);
    g_eoff[e] = atomicAdd(&g_deg[d], 1);
}

// ---------------- GEMM1: tensor-core HMMA, 128 rows/block, N=136 (h1 + attn dots) ----------------
__global__ void __launch_bounds__(256) k_gemm1(const float* __restrict__ x) {
    __shared__ __align__(16) __half As[128 * LDA];
    __shared__ __align__(16) __half Bs[16 * LDB];
    int t = threadIdx.x, lane = t & 31, warp = t >> 5;
    int row0 = blockIdx.x * 128;

    // stage A: 128 rows of x, fp32 -> fp16
    for (int i = t; i < 128 * 32; i += 256) {
        int r = i >> 5, c4 = i & 31;
        int gr = min(row0 + r, NN - 1);
        float4 v = ((const float4*)x)[gr * 32 + c4];
        *(__half2*)&As[r * LDA + c4 * 4]     = __floats2half2_rn(v.x, v.y);
        *(__half2*)&As[r * LDA + c4 * 4 + 2] = __floats2half2_rn(v.z, v.w);
    }

    float acc[17][4];
#pragma unroll
    for (int p = 0; p < 17; p++)
#pragma unroll
        for (int q = 0; q < 4; q++) acc[p][q] = 0.f;

    int wrow = warp * 16;
    uint32_t a_row_addr = smem_u32(&As[(wrow + (lane & 15)) * LDA + ((lane >> 4) * 8)]);
    uint32_t b_addr0 = (lane < 16) ? smem_u32(&Bs[(lane & 15) * LDB])
                                   : smem_u32(&Bs[(lane - 16) * LDB + 8]);

    for (int kb = 0; kb < 8; kb++) {
        __syncthreads();   // Bs safe to overwrite (and A staged on first iter)
        // stage B k-slice: 16 x 144 halfs = 288 uint4
        for (int i = t; i < 288; i += 256) {
            int r = i / 18, c8 = i % 18;
            uint4 v = ((const uint4*)&g_W1h[(kb * 16 + r) * 144])[c8];
            *(uint4*)&Bs[r * LDB + c8 * 8] = v;
        }
        __syncthreads();

        uint32_t a0, a1, a2, a3;
        ldmatrix_x4(a0, a1, a2, a3, a_row_addr + kb * 32);   // 16 halfs = 32 bytes per kb

#pragma unroll
        for (int p = 0; p < 9; p++) {
            uint32_t b0, b1, b2, b3;
            ldmatrix_x4_trans(b0, b1, b2, b3, b_addr0 + p * 32);  // n0 = p*16 -> 32B
            mma16816(acc[2 * p], a0, a1, a2, a3, b0, b1);
            if (p < 8) mma16816(acc[2 * p + 1], a0, a1, a2, a3, b2, b3);
        }
    }
    __syncthreads();   // done reading As

    int g = lane >> 2, c0 = (lane & 3) * 2;

    // attn-dot columns (tile 16 = cols 128..135): cols 0-3 -> as1 heads, 4-7 -> ad1 heads
    {
        int r_lo = row0 + wrow + g, r_hi = r_lo + 8;
#pragma unroll
        for (int q = 0; q < 4; q++) {
            int row = (q < 2) ? r_lo : r_hi;
            int c = c0 + (q & 1);
            if (row < NN) {
                if (c < 4) ((float*)&g_as1[row])[c] = acc[16][q];
                else       ((float*)&g_ad1[row])[c - 4] = acc[16][q];
            }
        }
    }

    // stage h1 (cols 0..127) as fp16 into As, then coalesced store
#pragma unroll
    for (int tl = 0; tl < 16; tl++) {
        *(__half2*)&As[(wrow + g) * LDA + tl * 8 + c0]     = __floats2half2_rn(acc[tl][0], acc[tl][1]);
        *(__half2*)&As[(wrow + g + 8) * LDA + tl * 8 + c0] = __floats2half2_rn(acc[tl][2], acc[tl][3]);
    }
    __syncthreads();
    for (int i = t; i < 128 * 16; i += 256) {
        int r = i >> 4, c16 = i & 15;
        int row = row0 + r;
        if (row < NN) ((uint4*)g_h1)[row * 16 + c16] = *(const uint4*)&As[r * LDA + c16 * 8];
    }
}

// ---------------- CSR scan ----------------
__global__ void __launch_bounds__(1024) k_scanA() {
    __shared__ int wsum[32];
    int t = threadIdx.x, lane = t & 31, wid = t >> 5;
    int i = blockIdx.x * 1024 + t;
    int v = (i < NN) ? g_deg[i] : 0;
    int s = v;
#pragma unroll
    for (int o = 1; o < 32; o <<= 1) {
        int n = __shfl_up_sync(0xffffffffu, s, o);
        if (lane >= o) s += n;
    }
    if (lane == 31) wsum[wid] = s;
    __syncthreads();
    if (wid == 0) {
        int ws = wsum[lane];
#pragma unroll
        for (int o = 1; o < 32; o <<= 1) {
            int n = __shfl_up_sync(0xffffffffu, ws, o);
            if (lane >= o) ws += n;
        }
        wsum[lane] = ws;
    }
    __syncthreads();
    int res = s + (wid ? wsum[wid - 1] : 0);
    if (i < NN) g_incl[i] = res;
    if (t == 1023) g_bsum[blockIdx.x] = res;
}

__global__ void __launch_bounds__(256) k_scanBC() {
    __shared__ int s_bscan[64];
    int t = threadIdx.x;
    if (t < 32) {
        int lane = t;
        int a = (lane < NB) ? g_bsum[lane] : 0;
#pragma unroll
        for (int o = 1; o < 32; o <<= 1) {
            int n = __shfl_up_sync(0xffffffffu, a, o);
            if (lane >= o) a += n;
        }
        int tot = __shfl_sync(0xffffffffu, a, 31);
        int b = (32 + lane < NB) ? g_bsum[32 + lane] : 0;
#pragma unroll
        for (int o = 1; o < 32; o <<= 1) {
            int n = __shfl_up_sync(0xffffffffu, b, o);
            if (lane >= o) b += n;
        }
        s_bscan[lane] = a;
        s_bscan[32 + lane] = b + tot;
    }
    __syncthreads();
    int i = blockIdx.x * 256 + t;
    if (i >= NN) return;
    int b = i >> 10;
    g_ptr[i] = g_incl[i] - g_deg[i] + (b ? s_bscan[b - 1] : 0);
}

__global__ void k_fill(const int* __restrict__ ei) {
    int e = blockIdx.x * blockDim.x + threadIdx.x;
    if (e >= ET) return;
    int s, d; edge_sd(ei, e, s, d);
    g_esrc[g_ptr[d] + g_eoff[e]] = s;
}

// ---------------- layer-1 aggregation: single pass, one warp per dst node ----------------
__global__ void __launch_bounds__(256) k_agg1() {
    __shared__ int    s_src[8][32];
    __shared__ float4 s_al[8][32];
    int gw = (blockIdx.x * 256 + threadIdx.x) >> 5;
    if (gw >= NN) return;
    int lane = threadIdx.x & 31;
    int wb = threadIdx.x >> 5;

    int beg = g_ptr[gw], deg = g_deg[gw];
    float4 ad = g_ad1[gw];

    float4 acc = make_float4(0.f, 0.f, 0.f, 0.f);
    float4 dsl = make_float4(0.f, 0.f, 0.f, 0.f);
    int head = lane >> 3;

    for (int base = 0; base < deg; base += 32) {
        int cnt = min(32, deg - base);
        if (lane < cnt) {
            int s = g_esrc[beg + base + lane];
            s_src[wb][lane] = s;
            float4 a = g_as1[s];
            float4 ev;
            ev.x = __expf(lrelu(a.x + ad.x));
            ev.y = __expf(lrelu(a.y + ad.y));
            ev.z = __expf(lrelu(a.z + ad.z));
            ev.w = __expf(lrelu(a.w + ad.w));
            s_al[wb][lane] = ev;
            dsl.x += ev.x; dsl.y += ev.y; dsl.z += ev.z; dsl.w += ev.w;
        }
        __syncwarp();
#pragma unroll 4
        for (int j = 0; j < cnt; j++) {
            int s = s_src[wb][j];
            float ev = ((float*)&s_al[wb][j])[head];
            uint2 hv = g_h1[s * 32 + lane];
            float2 lo = __half22float2(*(__half2*)&hv.x);
            float2 hi = __half22float2(*(__half2*)&hv.y);
            acc.x += lo.x * ev;
            acc.y += lo.y * ev;
            acc.z += hi.x * ev;
            acc.w += hi.y * ev;
        }
        __syncwarp();
    }

#pragma unroll
    for (int o = 16; o; o >>= 1) {
        dsl.x += __shfl_xor_sync(0xffffffffu, dsl.x, o);
        dsl.y += __shfl_xor_sync(0xffffffffu, dsl.y, o);
        dsl.z += __shfl_xor_sync(0xffffffffu, dsl.z, o);
        dsl.w += __shfl_xor_sync(0xffffffffu, dsl.w, o);
    }
    float invh = __fdividef(1.f, ((float*)&dsl)[head]);
    acc.x *= invh; acc.y *= invh; acc.z *= invh; acc.w *= invh;
    g_acc1[gw * 32 + lane] = acc;
}

// ---------------- GEMM2: relu(acc1+b1) @ [W2|ws|wd] ----------------
__global__ void __launch_bounds__(352) k_gemm2(
    const float* __restrict__ W2, const float* __restrict__ b1)
{
    __shared__ float rs[32][132];
    __shared__ float w2s[128][42];
    int t = threadIdx.x;
    int row0 = blockIdx.x * 32;

    for (int i = t; i < 32 * 32; i += 352) {
        int r = i >> 5, kc = i & 31;
        int gr = min(row0 + r, NN - 1);
        float4 v = ((const float4*)(const float*)g_acc1)[gr * 32 + kc];
        float4 bv = ((const float4*)b1)[kc];
        rs[r][kc * 4 + 0] = fmaxf(v.x + bv.x, 0.f);
        rs[r][kc * 4 + 1] = fmaxf(v.y + bv.y, 0.f);
        rs[r][kc * 4 + 2] = fmaxf(v.z + bv.z, 0.f);
        rs[r][kc * 4 + 3] = fmaxf(v.w + bv.w, 0.f);
    }
    for (int i = t; i < 128 * 42; i += 352) {
        int k = i / 42, c = i - k * 42;
        float v;
        if (c < OD)       v = W2[k * OD + c];
        else if (c == OD) v = g_wsd[k].x;
        else              v = g_wsd[k].y;
        w2s[k][c] = v;
    }
    __syncthreads();

    if (t < 336) {
        int c = t % 42, g = t / 42;
        int r0 = g * 4;
        float acc[4] = {0.f, 0.f, 0.f, 0.f};
        for (int k = 0; k < 128; k += 4) {
            float w0 = w2s[k][c], w1 = w2s[k + 1][c], w2v = w2s[k + 2][c], w3 = w2s[k + 3][c];
#pragma unroll
            for (int r = 0; r < 4; r++) {
                float4 xr = *(const float4*)&rs[r0 + r][k];
                acc[r] += xr.x * w0;
                acc[r] += xr.y * w1;
                acc[r] += xr.z * w2v;
                acc[r] += xr.w * w3;
            }
        }
#pragma unroll
        for (int r = 0; r < 4; r++) {
            int row = row0 + r0 + r;
            if (row < NN) {
                if (c < OD)       g_h2[row * OD + c] = __float2half_rn(acc[r]);
                else if (c == OD) g_as2[row] = acc[r];
                else              g_ad2[row] = acc[r];
            }
        }
    }
}

// ---------------- layer-2 aggregation: single pass, one warp per dst node ----------------
__global__ void __launch_bounds__(256) k_agg2(float* __restrict__ out,
                                              const float* __restrict__ b2) {
    __shared__ int   s_src[8][32];
    __shared__ float s_al[8][32];
    int gw = (blockIdx.x * 256 + threadIdx.x) >> 5;
    if (gw >= NN) return;
    int lane = threadIdx.x & 31;
    int wb = threadIdx.x >> 5;

    int beg = g_ptr[gw], deg = g_deg[gw];
    float ad = g_ad2[gw];

    const __half2* h2p = (const __half2*)g_h2;
    float2 acc = make_float2(0.f, 0.f);
    float dsl = 0.f;

    for (int base = 0; base < deg; base += 32) {
        int cnt = min(32, deg - base);
        if (lane < cnt) {
            int s = g_esrc[beg + base + lane];
            s_src[wb][lane] = s;
            float ev = __expf(lrelu(g_as2[s] + ad));
            s_al[wb][lane] = ev;
            dsl += ev;
        }
        __syncwarp();
        if (lane < 20) {
#pragma unroll 4
            for (int j = 0; j < cnt; j++) {
                int s = s_src[wb][j];
                float ev = s_al[wb][j];
                float2 h = __half22float2(h2p[s * 20 + lane]);
                acc.x += h.x * ev;
                acc.y += h.y * ev;
            }
        }
        __syncwarp();
    }

#pragma unroll
    for (int o = 16; o; o >>= 1) dsl += __shfl_xor_sync(0xffffffffu, dsl, o);
    float inv = __fdividef(1.f, dsl);

    if (lane < 20) {
        float2 bv = ((const float2*)b2)[lane];
        acc.x = acc.x * inv + bv.x;
        acc.y = acc.y * inv + bv.y;
        ((float2*)out)[gw * 20 + lane] = acc;
    }
}

// ---------------- launcher ----------------
extern "C" void kernel_launch(void* const* d_in, const int* in_sizes, int n_in,
                              void* d_out, int out_size)
{
    const float* x   = (const float*)d_in[0];
    const int*   ei  = (const int*)d_in[1];
    const float* W1  = (const float*)d_in[2];
    const float* as1 = (const float*)d_in[3];
    const float* ad1 = (const float*)d_in[4];
    const float* b1  = (const float*)d_in[5];
    const float* W2  = (const float*)d_in[6];
    const float* as2 = (const float*)d_in[7];
    const float* ad2 = (const float*)d_in[8];
    const float* b2  = (const float*)d_in[9];
    float* out = (float*)d_out;

    const int TB  = 256;
    const int EB  = (ET + TB - 1) / TB;
    const int NBK = (NN + TB - 1) / TB;
    const int WBK = (NN * 32 + TB - 1) / TB;

    k_zero_prep<<<NBK, TB>>>(W1, as1, ad1, W2, as2, ad2);
    k_hist<<<EB, TB>>>(ei);
    k_gemm1<<<(NN + 127) / 128, 256>>>(x);
    k_scanA<<<NB, 1024>>>();
    k_scanBC<<<NBK, TB>>>();
    k_fill<<<EB, TB>>>(ei);
    k_agg1<<<WBK, TB>>>();
    k_gemm2<<<(NN + 31) / 32, 352>>>(W2, b1);
    k_agg2<<<WBK, TB>>>(out, b2);
}